// round 14
// baseline (speedup 1.0000x reference)
#include <cuda_runtime.h>
#include <cuda_bf16.h>
#include <cstdint>

#define NN 100000
#define NE 800000
#define DD 256

// ---------------- device scratch (no allocations allowed) ----------------
__device__ __align__(16) __nv_bfloat16 g_HsA[(size_t)NN * DD];  // layer-1 features (bf16)
__device__ __align__(16) __nv_bfloat16 g_HsB[(size_t)NN * DD];  // layer-2 features (bf16)
__device__ int   g_indeg[NN];
__device__ int   g_off[NN];
__device__ int   g_epos[NE];
__device__ int   g_csrc[NE];
__device__ int   g_total;
// W bf16, pre-transposed to [N][K] (B operand, K-contiguous)
__device__ __align__(16) __nv_bfloat16 g_W1h[256 * 256];
__device__ __align__(16) __nv_bfloat16 g_W2h[256 * 256];
__device__ __align__(16) __nv_bfloat16 g_Woh[64 * 256];

// ---------------- PTX helpers (valid on compute_103) ----------------
__device__ __forceinline__ uint32_t smem_u32(const void* p) {
    uint32_t a;
    asm("{ .reg .u64 t; cvta.to.shared.u64 t, %1; cvt.u32.u64 %0, t; }" : "=r"(a) : "l"(p));
    return a;
}
__device__ __forceinline__ void ldsm4(uint32_t r[4], uint32_t addr) {
    asm volatile("ldmatrix.sync.aligned.m8n8.x4.shared.b16 {%0,%1,%2,%3}, [%4];"
                 : "=r"(r[0]), "=r"(r[1]), "=r"(r[2]), "=r"(r[3]) : "r"(addr));
}
__device__ __forceinline__ void mma16816(float c[4], const uint32_t a[4],
                                         uint32_t b0, uint32_t b1) {
    asm volatile(
        "mma.sync.aligned.m16n8k16.row.col.f32.bf16.bf16.f32 "
        "{%0,%1,%2,%3}, {%4,%5,%6,%7}, {%8,%9}, {%0,%1,%2,%3};"
        : "+f"(c[0]), "+f"(c[1]), "+f"(c[2]), "+f"(c[3])
        : "r"(a[0]), "r"(a[1]), "r"(a[2]), "r"(a[3]), "r"(b0), "r"(b1));
}
__device__ __forceinline__ void cpa16(uint32_t dst, const void* src) {
    asm volatile("cp.async.cg.shared.global [%0], [%1], 16;"
                 :: "r"(dst), "l"(src) : "memory");
}
#define CP_COMMIT() asm volatile("cp.async.commit_group;" ::: "memory")
#define CP_WAIT(n)  asm volatile("cp.async.wait_group %0;" :: "n"(n) : "memory")

__device__ __forceinline__ void sts128(uint32_t addr, uint4 v) {
    asm volatile("st.shared.v4.b32 [%0], {%1,%2,%3,%4};"
                 :: "r"(addr), "r"(v.x), "r"(v.y), "r"(v.z), "r"(v.w) : "memory");
}
__device__ __forceinline__ uint32_t packbf2(float f0, float f1) {
    __nv_bfloat16 h0 = __float2bfloat16(f0), h1 = __float2bfloat16(f1);
    return (uint32_t)*(uint16_t*)&h0 | ((uint32_t)*(uint16_t*)&h1 << 16);
}
__device__ __forceinline__ float2 bf2f(uint32_t w) {
    __nv_bfloat162 b;
    *reinterpret_cast<uint32_t*>(&b) = w;
    return __bfloat1622float2(b);
}
__device__ __forceinline__ void acc8(float* a, uint4 u) {
    float2 f0 = bf2f(u.x), f1 = bf2f(u.y), f2 = bf2f(u.z), f3 = bf2f(u.w);
    a[0] += f0.x; a[1] += f0.y; a[2] += f1.x; a[3] += f1.y;
    a[4] += f2.x; a[5] += f2.y; a[6] += f3.x; a[7] += f3.y;
}

// ---------------- prep: W->bf16 transposed, zero deg ----------------
__global__ void k_prep(const float* __restrict__ W1, const float* __restrict__ W2,
                       const float* __restrict__ Wo) {
    int gid = blockIdx.x * 256 + threadIdx.x;
    if (gid < NN) g_indeg[gid] = 0;
    if (gid == 0) g_total = 0;
    if (gid < 65536) {
        int n = gid >> 8, k = gid & 255;
        g_W1h[gid] = __float2bfloat16(W1[(size_t)k * 256 + n]);
        g_W2h[gid] = __float2bfloat16(W2[(size_t)k * 256 + n]);
        if (gid < 16384) {
            int n2 = gid >> 8, k2 = gid & 255;
            g_Woh[gid] = __float2bfloat16(Wo[(size_t)k2 * 64 + n2]);
        }
    }
}
// degree count + per-edge slot reservation
__global__ void k_deg(const int* __restrict__ dst) {
    int e = blockIdx.x * 256 + threadIdx.x;
    if (e < NE) g_epos[e] = atomicAdd(&g_indeg[dst[e]], 1);
}
// parallel offset assignment: warp scan + one atomic per warp (order-free CSR)
__global__ void k_off() {
    int i = blockIdx.x * 256 + threadIdx.x;
    int lane = threadIdx.x & 31;
    int d = (i < NN) ? g_indeg[i] : 0;
    int v = d;
    #pragma unroll
    for (int s = 1; s < 32; s <<= 1) {
        int t = __shfl_up_sync(0xffffffffu, v, s);
        if (lane >= s) v += t;
    }
    int wtotal = __shfl_sync(0xffffffffu, v, 31);
    int base = 0;
    if (lane == 0) base = atomicAdd(&g_total, wtotal);
    base = __shfl_sync(0xffffffffu, base, 0);
    if (i < NN) g_off[i] = base + v - d;
}
// atomic-free scatter using reserved slots
__global__ void k_scatter(const int* __restrict__ src, const int* __restrict__ dst) {
    int e = blockIdx.x * 256 + threadIdx.x;
    if (e < NE) g_csrc[g_off[dst[e]] + g_epos[e]] = src[e];
}

// ---------------- fused GEMM: resident-A smem + 4-stage B ring ----------------
// MODE 0: A = bf16(x) inline from fp32;       C = g_HsA (dis-scaled), N=256
// MODE 1: A = gather(g_HsA)+relu(..+b1);      C = g_HsB (dis-scaled), N=256
// MODE 2: A = gather(g_HsB)+relu(..+b2);      C = out (bias + log_softmax), N=64
// BM=128. N swept in halves of 128 (MODE2: one pass of 64). 256 thr, 2 CTAs/SM.
template <int MODE>
__global__ __launch_bounds__(256, 2)
void gemm_fused(const float* __restrict__ xin, const float* __restrict__ bias_agg,
                const float* __restrict__ bias_out, float* __restrict__ Cext)
{
    const __nv_bfloat16* WH = (MODE == 0) ? g_W1h : (MODE == 1) ? g_W2h : g_Woh;
    const __nv_bfloat16* __restrict__ Hsrc = (MODE == 1) ? g_HsA : g_HsB;  // gather src
    __nv_bfloat16* Hdst = (MODE == 0) ? g_HsA : g_HsB;                    // epilogue dst

    constexpr int BNH = (MODE == 2) ? 64 : 128;   // N per pass
    constexpr int NH  = (MODE == 2) ? 1 : 2;      // passes
    constexpr int WN  = BNH / 2;                  // 64 or 32
    constexpr int NT  = WN / 8;                   // 8 or 4
    constexpr int BH  = BNH / 64;                 // B cp.async iters (2 or 1)
    constexpr int BSTAGE = BNH * 80;
    constexpr int ARES = 128 * 528;               // 67584 B resident A

    extern __shared__ char smraw[];
    uint32_t sb = smem_u32(smraw);
    uint32_t sbA = sb, sbB = sb + ARES;

    int tid = threadIdx.x, lane = tid & 31, wid = tid >> 5;
    int mw = wid & 3, nw = wid >> 2;
    int bm0 = blockIdx.x * 128;

    auto issueB = [&](int kb, int bn0) {
        uint32_t base = sbB + (uint32_t)(kb & 3) * BSTAGE;
        #pragma unroll
        for (int h = 0; h < BH; h++) {
            int c = tid + h * 256;
            int row = c >> 2, kq = c & 3;
            cpa16(base + (uint32_t)row * 80u + (uint32_t)kq * 16u,
                  WH + (size_t)(bn0 + row) * DD + kb * 32 + kq * 8);
        }
        CP_COMMIT();
    };

    // B prologue for pass 0 (async, overlaps A build)
    issueB(0, 0); issueB(1, 0); issueB(2, 0);

    // ---- build resident A tile ----
    if (MODE == 0) {
        int row = tid >> 1, half = tid & 1;
        int r = bm0 + row;
        const float* xp = xin + (size_t)r * DD + half * 128;
        uint32_t arow = sbA + (uint32_t)row * 528u + (uint32_t)half * 256u;
        bool ok = (r < NN);
        #pragma unroll
        for (int g = 0; g < 16; g++) {
            float4 v0 = ok ? *(const float4*)(xp + g * 8) : make_float4(0.f, 0.f, 0.f, 0.f);
            float4 v1 = ok ? *(const float4*)(xp + g * 8 + 4) : make_float4(0.f, 0.f, 0.f, 0.f);
            uint4 p = make_uint4(packbf2(v0.x, v0.y), packbf2(v0.z, v0.w),
                                 packbf2(v1.x, v1.y), packbf2(v1.z, v1.w));
            sts128(arow + g * 16, p);
        }
    } else {
        float4 bb0 = *(const float4*)(bias_agg + lane * 8);
        float4 bb1 = *(const float4*)(bias_agg + lane * 8 + 4);
        #pragma unroll 1
        for (int it = 0; it < 16; it++) {
            int row = wid * 16 + it;
            int node = bm0 + row;
            uint32_t dstb = sbA + (uint32_t)row * 528u + (uint32_t)lane * 16u;
            if (node < NN) {
                float a[8];
                {
                    uint4 u = *(const uint4*)(Hsrc + (size_t)node * 256 + lane * 8);
                    float2 f0 = bf2f(u.x), f1 = bf2f(u.y), f2 = bf2f(u.z), f3 = bf2f(u.w);
                    a[0] = f0.x; a[1] = f0.y; a[2] = f1.x; a[3] = f1.y;
                    a[4] = f2.x; a[5] = f2.y; a[6] = f3.x; a[7] = f3.y;
                }
                int e = g_off[node], deg = g_indeg[node], end = e + deg;
                for (; e + 3 < end; e += 4) {
                    int s0 = g_csrc[e], s1 = g_csrc[e + 1];
                    int s2 = g_csrc[e + 2], s3 = g_csrc[e + 3];
                    uint4 u0 = *(const uint4*)(Hsrc + (size_t)s0 * 256 + lane * 8);
                    uint4 u1 = *(const uint4*)(Hsrc + (size_t)s1 * 256 + lane * 8);
                    uint4 u2 = *(const uint4*)(Hsrc + (size_t)s2 * 256 + lane * 8);
                    uint4 u3 = *(const uint4*)(Hsrc + (size_t)s3 * 256 + lane * 8);
                    acc8(a, u0); acc8(a, u1); acc8(a, u2); acc8(a, u3);
                }
                for (; e < end; e++) {
                    uint4 u0 = *(const uint4*)(Hsrc + (size_t)g_csrc[e] * 256 + lane * 8);
                    acc8(a, u0);
                }
                float dsc = rsqrtf((float)(deg + 1));
                float o0 = fmaxf(fmaf(dsc, a[0], bb0.x), 0.f);
                float o1 = fmaxf(fmaf(dsc, a[1], bb0.y), 0.f);
                float o2 = fmaxf(fmaf(dsc, a[2], bb0.z), 0.f);
                float o3 = fmaxf(fmaf(dsc, a[3], bb0.w), 0.f);
                float o4 = fmaxf(fmaf(dsc, a[4], bb1.x), 0.f);
                float o5 = fmaxf(fmaf(dsc, a[5], bb1.y), 0.f);
                float o6 = fmaxf(fmaf(dsc, a[6], bb1.z), 0.f);
                float o7 = fmaxf(fmaf(dsc, a[7], bb1.w), 0.f);
                sts128(dstb, make_uint4(packbf2(o0, o1), packbf2(o2, o3),
                                        packbf2(o4, o5), packbf2(o6, o7)));
            } else {
                sts128(dstb, make_uint4(0u, 0u, 0u, 0u));
            }
        }
    }

    float acc[2][NT][4];

    #pragma unroll 1
    for (int half = 0; half < NH; half++) {
        int bn0 = half * BNH;
        if (half > 0) {
            CP_WAIT(0);
            __syncthreads();
            issueB(0, bn0); issueB(1, bn0); issueB(2, bn0);
        }
        #pragma unroll
        for (int mt = 0; mt < 2; mt++)
            #pragma unroll
            for (int nt = 0; nt < NT; nt++)
                #pragma unroll
                for (int q = 0; q < 4; q++) acc[mt][nt][q] = 0.f;

        for (int kb = 0; kb < 8; kb++) {
            CP_WAIT(2);
            __syncthreads();
            if (kb < 5) issueB(kb + 3, bn0); else CP_COMMIT();

            uint32_t base = sbB + (uint32_t)(kb & 3) * BSTAGE;
            #pragma unroll
            for (int ks = 0; ks < 2; ks++) {
                int col = ks * 16 + (lane >> 4) * 8;
                uint32_t ah[2][4];
                uint32_t aoff = sbA + (uint32_t)((mw * 32 + (lane & 15)) * 528)
                              + (uint32_t)(kb * 32 + col) * 2u;
                ldsm4(ah[0], aoff);
                ldsm4(ah[1], aoff + 16 * 528);

                #pragma unroll
                for (int g = 0; g < NT / 4; g++) {
                    uint32_t bh[4][2];
                    #pragma unroll
                    for (int j2 = 0; j2 < 2; j2++) {
                        int j = g * 2 + j2;
                        uint32_t boff = base +
                            (uint32_t)((nw * WN + j * 16 + (lane & 15)) * 80) +
                            (uint32_t)col * 2u;
                        uint32_t rh[4];
                        ldsm4(rh, boff);
                        bh[2 * j2][0] = rh[0]; bh[2 * j2][1] = rh[2];
                        bh[2 * j2 + 1][0] = rh[1]; bh[2 * j2 + 1][1] = rh[3];
                    }
                    #pragma unroll
                    for (int mt = 0; mt < 2; mt++)
                        #pragma unroll
                        for (int q = 0; q < 4; q++)
                            mma16816(acc[mt][g * 4 + q], ah[mt], bh[q][0], bh[q][1]);
                }
            }
        }

        if (MODE != 2) {
            // per-half epilogue: dis scale + bf16 store (to the OTHER buffer)
            int rbase = bm0 + mw * 32 + (lane >> 2);
            int cbase = bn0 + nw * WN + (lane & 3) * 2;
            #pragma unroll
            for (int mt = 0; mt < 2; mt++) {
                int r0 = rbase + mt * 16, r1 = r0 + 8;
                float s0 = (r0 < NN) ? rsqrtf((float)(g_indeg[r0] + 1)) : 0.f;
                float s1 = (r1 < NN) ? rsqrtf((float)(g_indeg[r1] + 1)) : 0.f;
                #pragma unroll
                for (int nt = 0; nt < NT; nt++) {
                    int cc = cbase + nt * 8;
                    if (r0 < NN) *(uint32_t*)(Hdst + (size_t)r0 * 256 + cc) =
                        packbf2(acc[mt][nt][0] * s0, acc[mt][nt][1] * s0);
                    if (r1 < NN) *(uint32_t*)(Hdst + (size_t)r1 * 256 + cc) =
                        packbf2(acc[mt][nt][2] * s1, acc[mt][nt][3] * s1);
                }
            }
        }
    }

    if (MODE == 2) {
        // bias -> smem (reuse A region) -> fused log_softmax -> fp32 store
        __syncthreads();
        float* ls = (float*)smraw;   // 128 x 64 fp32 = 32KB (A region done)
        int lr0 = mw * 32 + (lane >> 2);
        int cb = nw * WN + (lane & 3) * 2;
        #pragma unroll
        for (int mt = 0; mt < 2; mt++) {
            int a0 = lr0 + mt * 16, a1 = a0 + 8;
            #pragma unroll
            for (int nt = 0; nt < NT; nt++) {
                int cc = cb + nt * 8;
                float b0 = bias_out[cc], b1 = bias_out[cc + 1];
                ls[a0 * 64 + cc] = acc[mt][nt][0] + b0;
                ls[a0 * 64 + cc + 1] = acc[mt][nt][1] + b1;
                ls[a1 * 64 + cc] = acc[mt][nt][2] + b0;
                ls[a1 * 64 + cc + 1] = acc[mt][nt][3] + b1;
            }
        }
        __syncthreads();
        #pragma unroll 1
        for (int i = 0; i < 16; i++) {
            int lr = wid * 16 + i;
            int r = bm0 + lr;
            if (r >= NN) break;
            float2 v = *(const float2*)&ls[lr * 64 + lane * 2];
            float m = fmaxf(v.x, v.y);
            #pragma unroll
            for (int d = 16; d; d >>= 1) m = fmaxf(m, __shfl_xor_sync(0xffffffffu, m, d));
            float sm = expf(v.x - m) + expf(v.y - m);
            #pragma unroll
            for (int d = 16; d; d >>= 1) sm += __shfl_xor_sync(0xffffffffu, sm, d);
            float l = m + logf(sm);
            *(float2*)(Cext + (size_t)r * 64 + lane * 2) = make_float2(v.x - l, v.y - l);
        }
    }
}

// ---------------- launch ----------------
extern "C" void kernel_launch(void* const* d_in, const int* in_sizes, int n_in,
                              void* d_out, int out_size)
{
    const float* x  = (const float*)d_in[0];
    const int*   ei = (const int*)d_in[1];
    const float* W1 = (const float*)d_in[2];
    const float* b1 = (const float*)d_in[3];
    const float* W2 = (const float*)d_in[4];
    const float* b2 = (const float*)d_in[5];
    const float* Wo = (const float*)d_in[6];
    const float* bo = (const float*)d_in[7];
    float* out = (float*)d_out;

    const int* src = ei;
    const int* dst = ei + NE;

    constexpr int SM01 = 128 * 528 + 4 * 128 * 80;   // 108544
    constexpr int SM2  = 128 * 528 + 4 * 64 * 80;    // 88064
    cudaFuncSetAttribute(gemm_fused<0>, cudaFuncAttributeMaxDynamicSharedMemorySize, SM01);
    cudaFuncSetAttribute(gemm_fused<1>, cudaFuncAttributeMaxDynamicSharedMemorySize, SM01);
    cudaFuncSetAttribute(gemm_fused<2>, cudaFuncAttributeMaxDynamicSharedMemorySize, SM2);

    const int GM = (NN + 127) / 128;   // 782

    k_prep<<<(NN + 255) / 256, 256>>>(W1, W2, Wo);               // 1: W bf16 + zero deg
    k_deg<<<NE / 256, 256>>>(dst);                               // 2: degrees + edge slots
    k_off<<<(NN + 255) / 256, 256>>>();                          // 3: CSR offsets
    gemm_fused<0><<<GM, 256, SM01>>>(x, nullptr, nullptr, nullptr);   // 4: HsA = dis*(x@W1)
    k_scatter<<<NE / 256, 256>>>(src, dst);                      // 5: CSR fill (no atomics)
    gemm_fused<1><<<GM, 256, SM01>>>(nullptr, b1, nullptr, nullptr);  // 6: HsB = dis*(agg(HsA)@W2)
    gemm_fused<2><<<GM, 256, SM2>>>(nullptr, b2, bo, out);       // 7: out = lsm(agg(HsB)@Wo+bo)
}

// round 15
// speedup vs baseline: 1.2706x; 1.2706x over previous
#include <cuda_runtime.h>
#include <cuda_bf16.h>
#include <cstdint>

#define NN 100000
#define NE 800000
#define DD 256

// ---------------- device scratch (no allocations allowed) ----------------
__device__ __align__(16) __nv_bfloat16 g_Hs[(size_t)NN * DD];   // dis-scaled h (bf16)
__device__ __align__(16) __nv_bfloat16 g_Ah[(size_t)NN * DD];   // A operand bf16 (x / relu out)
__device__ int   g_indeg[NN];
__device__ int   g_off[NN];
__device__ int   g_epos[NE];
__device__ int   g_csrc[NE];
__device__ int   g_total;
// W bf16, pre-transposed to [N][K] (B operand, K-contiguous)
__device__ __align__(16) __nv_bfloat16 g_W1h[256 * 256];
__device__ __align__(16) __nv_bfloat16 g_W2h[256 * 256];
__device__ __align__(16) __nv_bfloat16 g_Woh[64 * 256];

// ---------------- PTX helpers (valid on compute_103) ----------------
__device__ __forceinline__ uint32_t smem_u32(const void* p) {
    uint32_t a;
    asm("{ .reg .u64 t; cvta.to.shared.u64 t, %1; cvt.u32.u64 %0, t; }" : "=r"(a) : "l"(p));
    return a;
}
__device__ __forceinline__ void ldsm4(uint32_t r[4], uint32_t addr) {
    asm volatile("ldmatrix.sync.aligned.m8n8.x4.shared.b16 {%0,%1,%2,%3}, [%4];"
                 : "=r"(r[0]), "=r"(r[1]), "=r"(r[2]), "=r"(r[3]) : "r"(addr));
}
__device__ __forceinline__ void mma16816(float c[4], const uint32_t a[4],
                                         uint32_t b0, uint32_t b1) {
    asm volatile(
        "mma.sync.aligned.m16n8k16.row.col.f32.bf16.bf16.f32 "
        "{%0,%1,%2,%3}, {%4,%5,%6,%7}, {%8,%9}, {%0,%1,%2,%3};"
        : "+f"(c[0]), "+f"(c[1]), "+f"(c[2]), "+f"(c[3])
        : "r"(a[0]), "r"(a[1]), "r"(a[2]), "r"(a[3]), "r"(b0), "r"(b1));
}
__device__ __forceinline__ void cpa16(uint32_t dst, const void* src, int sz) {
    asm volatile("cp.async.cg.shared.global [%0], [%1], 16, %2;"
                 :: "r"(dst), "l"(src), "r"(sz) : "memory");
}
#define CP_COMMIT() asm volatile("cp.async.commit_group;" ::: "memory")
#define CP_WAIT(n)  asm volatile("cp.async.wait_group %0;" :: "n"(n) : "memory")

// pack two fp32 -> one bf16x2 word (round-to-nearest)
__device__ __forceinline__ uint32_t packbf2(float f0, float f1) {
    __nv_bfloat16 h0 = __float2bfloat16(f0), h1 = __float2bfloat16(f1);
    return (uint32_t)*(uint16_t*)&h0 | ((uint32_t)*(uint16_t*)&h1 << 16);
}
__device__ __forceinline__ float2 bf2f(uint32_t w) {
    __nv_bfloat162 b;
    *reinterpret_cast<uint32_t*>(&b) = w;
    return __bfloat1622float2(b);
}
__device__ __forceinline__ void acc8(float* a, uint4 u) {
    float2 f0 = bf2f(u.x), f1 = bf2f(u.y), f2 = bf2f(u.z), f3 = bf2f(u.w);
    a[0] += f0.x; a[1] += f0.y; a[2] += f1.x; a[3] += f1.y;
    a[4] += f2.x; a[5] += f2.y; a[6] += f3.x; a[7] += f3.y;
}

// ---------------- prep: x->bf16, W->bf16 transposed, zero deg ----------------
__global__ void k_prep(const float* __restrict__ x, const float* __restrict__ W1,
                       const float* __restrict__ W2, const float* __restrict__ Wo) {
    int gid = blockIdx.x * 256 + threadIdx.x;
    size_t i = (size_t)gid * 4;
    float4 v = *(const float4*)(x + i);
    *(uint2*)(g_Ah + i) = make_uint2(packbf2(v.x, v.y), packbf2(v.z, v.w));

    if (gid < NN) g_indeg[gid] = 0;
    if (gid == 0) g_total = 0;
    if (gid < 65536) {
        int n = gid >> 8, k = gid & 255;
        g_W1h[gid] = __float2bfloat16(W1[(size_t)k * 256 + n]);
        g_W2h[gid] = __float2bfloat16(W2[(size_t)k * 256 + n]);
        if (gid < 16384) {
            int n2 = gid >> 8, k2 = gid & 255;
            g_Woh[gid] = __float2bfloat16(Wo[(size_t)k2 * 64 + n2]);
        }
    }
}
// degree count + per-edge slot reservation
__global__ void k_deg(const int* __restrict__ dst) {
    int e = blockIdx.x * 256 + threadIdx.x;
    if (e < NE) g_epos[e] = atomicAdd(&g_indeg[dst[e]], 1);
}
// parallel offset assignment: warp scan + one atomic per warp (order-free CSR)
__global__ void k_off() {
    int i = blockIdx.x * 256 + threadIdx.x;
    int lane = threadIdx.x & 31;
    int d = (i < NN) ? g_indeg[i] : 0;
    int v = d;
    #pragma unroll
    for (int s = 1; s < 32; s <<= 1) {
        int t = __shfl_up_sync(0xffffffffu, v, s);
        if (lane >= s) v += t;
    }
    int wtotal = __shfl_sync(0xffffffffu, v, 31);
    int base = 0;
    if (lane == 0) base = atomicAdd(&g_total, wtotal);
    base = __shfl_sync(0xffffffffu, base, 0);
    if (i < NN) g_off[i] = base + v - d;
}
// atomic-free scatter using reserved slots
__global__ void k_scatter(const int* __restrict__ src, const int* __restrict__ dst) {
    int e = blockIdx.x * 256 + threadIdx.x;
    if (e < NE) g_csrc[g_off[dst[e]] + g_epos[e]] = src[e];
}

// ---------------- HMMA GEMM, 4-stage cp.async ring, single bf16 pass ---------
// BM=128, BK=32, 256 thr (8 warps 4m x 2n), warp tile 32 x (BN/2). 2 CTAs/SM.
// MODE 0/1: C=g_Hs (bf16), row-scale by rsqrt(indeg+1)
// MODE 2:   C=Cext (fp32), + bias + fused log_softmax (BN=64)
template <int MODE, int BN>
__global__ __launch_bounds__(256, 2)
void gemm_mma(const float* __restrict__ bias, float* __restrict__ Cext)
{
    const __nv_bfloat16* WH = (MODE == 0) ? g_W1h : (MODE == 1) ? g_W2h : g_Woh;

    constexpr int WN = BN / 2;               // 64 or 32
    constexpr int NT = WN / 8;               // 8 or 4
    constexpr int A_BYTES = 128 * 80;        // 10240 (LDSE=40 elems, 80B rows)
    constexpr int B_BYTES = BN * 80;
    constexpr int STAGE = A_BYTES + B_BYTES;
    constexpr int BH = BN / 64;              // B cp.async iterations (2 or 1)

    extern __shared__ char smraw[];
    uint32_t sb = smem_u32(smraw);

    int tid = threadIdx.x, lane = tid & 31, wid = tid >> 5;
    int mw = wid & 3, nw = wid >> 2;
    int bm0 = blockIdx.x * 128;
    int bn0 = blockIdx.y * BN;

    auto issue = [&](int kb) {
        uint32_t base = sb + (uint32_t)(kb & 3) * STAGE;
        #pragma unroll
        for (int h = 0; h < 2; h++) {
            int c = tid + h * 256;
            int row = c >> 2, kq = c & 3;
            int r = bm0 + row;
            uint32_t dst = base + (uint32_t)row * 80u + (uint32_t)kq * 16u;
            size_t gp = (size_t)r * DD + kb * 32 + kq * 8;
            cpa16(dst, g_Ah + gp, (r < NN) ? 16 : 0);
        }
        #pragma unroll
        for (int h = 0; h < BH; h++) {
            int c = tid + h * 256;
            int row = c >> 2, kq = c & 3;
            uint32_t dst = base + A_BYTES + (uint32_t)row * 80u + (uint32_t)kq * 16u;
            size_t gp = (size_t)(bn0 + row) * DD + kb * 32 + kq * 8;
            cpa16(dst, WH + gp, 16);
        }
        CP_COMMIT();
    };

    float acc[2][NT][4];
    #pragma unroll
    for (int mt = 0; mt < 2; mt++)
        #pragma unroll
        for (int nt = 0; nt < NT; nt++)
            #pragma unroll
            for (int q = 0; q < 4; q++) acc[mt][nt][q] = 0.f;

    issue(0); issue(1); issue(2);

    for (int kb = 0; kb < 8; kb++) {
        CP_WAIT(2);            // chunk kb complete (tail kept aligned w/ empty groups)
        __syncthreads();       // all warps done with stage (kb+3)&3
        if (kb + 3 < 8) issue(kb + 3); else CP_COMMIT();

        uint32_t base = sb + (uint32_t)(kb & 3) * STAGE;
        #pragma unroll
        for (int ks = 0; ks < 2; ks++) {
            int col = ks * 16 + (lane >> 4) * 8;
            uint32_t ah[2][4];
            uint32_t aoff = (uint32_t)((mw * 32 + (lane & 15)) * 40 + col) * 2u;
            ldsm4(ah[0], base + aoff);
            ldsm4(ah[1], base + aoff + 16 * 80);

            #pragma unroll
            for (int g = 0; g < NT / 4; g++) {
                uint32_t bh[4][2];
                #pragma unroll
                for (int j2 = 0; j2 < 2; j2++) {
                    int j = g * 2 + j2;
                    uint32_t boff = base + A_BYTES +
                        (uint32_t)((nw * WN + j * 16 + (lane & 15)) * 40 + col) * 2u;
                    uint32_t rh[4];
                    ldsm4(rh, boff);
                    bh[2 * j2][0] = rh[0]; bh[2 * j2][1] = rh[2];
                    bh[2 * j2 + 1][0] = rh[1]; bh[2 * j2 + 1][1] = rh[3];
                }
                #pragma unroll
                for (int mt = 0; mt < 2; mt++)
                    #pragma unroll
                    for (int q = 0; q < 4; q++)
                        mma16816(acc[mt][g * 4 + q], ah[mt], bh[q][0], bh[q][1]);
            }
        }
    }

    if (MODE != 2) {
        // ---- epilogue: dis = rsqrt(indeg+1), scale + bf16 store to g_Hs ----
        int rbase = bm0 + mw * 32 + (lane >> 2);
        int cbase = bn0 + nw * WN + (lane & 3) * 2;
        #pragma unroll
        for (int mt = 0; mt < 2; mt++) {
            int r0 = rbase + mt * 16, r1 = r0 + 8;
            float s0 = (r0 < NN) ? rsqrtf((float)(g_indeg[r0] + 1)) : 0.f;
            float s1 = (r1 < NN) ? rsqrtf((float)(g_indeg[r1] + 1)) : 0.f;
            #pragma unroll
            for (int nt = 0; nt < NT; nt++) {
                int cc = cbase + nt * 8;
                if (r0 < NN) *(uint32_t*)(g_Hs + (size_t)r0 * 256 + cc) =
                    packbf2(acc[mt][nt][0] * s0, acc[mt][nt][1] * s0);
                if (r1 < NN) *(uint32_t*)(g_Hs + (size_t)r1 * 256 + cc) =
                    packbf2(acc[mt][nt][2] * s1, acc[mt][nt][3] * s1);
            }
        }
    } else {
        // ---- epilogue: bias -> smem -> fused log_softmax -> fp32 store ----
        __syncthreads();   // all compute done before smem reuse
        float* ls = (float*)smraw;   // 128 x 64 fp32 = 32KB
        int lr0 = mw * 32 + (lane >> 2);
        int cb = nw * WN + (lane & 3) * 2;
        #pragma unroll
        for (int mt = 0; mt < 2; mt++) {
            int a0 = lr0 + mt * 16, a1 = a0 + 8;
            #pragma unroll
            for (int nt = 0; nt < NT; nt++) {
                int cc = cb + nt * 8;
                float b0 = bias[cc], b1 = bias[cc + 1];
                ls[a0 * 64 + cc] = acc[mt][nt][0] + b0;
                ls[a0 * 64 + cc + 1] = acc[mt][nt][1] + b1;
                ls[a1 * 64 + cc] = acc[mt][nt][2] + b0;
                ls[a1 * 64 + cc + 1] = acc[mt][nt][3] + b1;
            }
        }
        __syncthreads();
        #pragma unroll 1
        for (int i = 0; i < 16; i++) {
            int lr = wid * 16 + i;
            int r = bm0 + lr;
            if (r >= NN) break;
            float2 v = *(const float2*)&ls[lr * 64 + lane * 2];
            float m = fmaxf(v.x, v.y);
            #pragma unroll
            for (int d = 16; d; d >>= 1) m = fmaxf(m, __shfl_xor_sync(0xffffffffu, m, d));
            float sm = expf(v.x - m) + expf(v.y - m);
            #pragma unroll
            for (int d = 16; d; d >>= 1) sm += __shfl_xor_sync(0xffffffffu, sm, d);
            float l = m + logf(sm);
            *(float2*)(Cext + (size_t)r * 64 + lane * 2) = make_float2(v.x - l, v.y - l);
        }
    }
}

// ---------------- aggregation (bf16 gather, MLP=8): relu(dis*(...)+b) -> bf16 ----
__global__ __launch_bounds__(256)
void k_agg(const float* __restrict__ bias)
{
    int node = blockIdx.x * 8 + (threadIdx.x >> 5);
    int lane = threadIdx.x & 31;
    const __nv_bfloat16* __restrict__ Hs = g_Hs;

    size_t self = (size_t)node * 256 + lane * 8;
    float a[8];
    {
        uint4 u = *(const uint4*)(Hs + self);
        float2 f0 = bf2f(u.x), f1 = bf2f(u.y), f2 = bf2f(u.z), f3 = bf2f(u.w);
        a[0] = f0.x; a[1] = f0.y; a[2] = f1.x; a[3] = f1.y;
        a[4] = f2.x; a[5] = f2.y; a[6] = f3.x; a[7] = f3.y;
    }

    int e = g_off[node], deg = g_indeg[node], end = e + deg;
    // 8-wide: 8 independent 16B gathers in flight per lane
    for (; e + 7 < end; e += 8) {
        uint4 u0 = *(const uint4*)(Hs + (size_t)g_csrc[e + 0] * 256 + lane * 8);
        uint4 u1 = *(const uint4*)(Hs + (size_t)g_csrc[e + 1] * 256 + lane * 8);
        uint4 u2 = *(const uint4*)(Hs + (size_t)g_csrc[e + 2] * 256 + lane * 8);
        uint4 u3 = *(const uint4*)(Hs + (size_t)g_csrc[e + 3] * 256 + lane * 8);
        uint4 u4 = *(const uint4*)(Hs + (size_t)g_csrc[e + 4] * 256 + lane * 8);
        uint4 u5 = *(const uint4*)(Hs + (size_t)g_csrc[e + 5] * 256 + lane * 8);
        uint4 u6 = *(const uint4*)(Hs + (size_t)g_csrc[e + 6] * 256 + lane * 8);
        uint4 u7 = *(const uint4*)(Hs + (size_t)g_csrc[e + 7] * 256 + lane * 8);
        acc8(a, u0); acc8(a, u1); acc8(a, u2); acc8(a, u3);
        acc8(a, u4); acc8(a, u5); acc8(a, u6); acc8(a, u7);
    }
    if (e + 3 < end) {
        uint4 u0 = *(const uint4*)(Hs + (size_t)g_csrc[e + 0] * 256 + lane * 8);
        uint4 u1 = *(const uint4*)(Hs + (size_t)g_csrc[e + 1] * 256 + lane * 8);
        uint4 u2 = *(const uint4*)(Hs + (size_t)g_csrc[e + 2] * 256 + lane * 8);
        uint4 u3 = *(const uint4*)(Hs + (size_t)g_csrc[e + 3] * 256 + lane * 8);
        acc8(a, u0); acc8(a, u1); acc8(a, u2); acc8(a, u3);
        e += 4;
    }
    for (; e < end; e++) {
        uint4 u0 = *(const uint4*)(Hs + (size_t)g_csrc[e] * 256 + lane * 8);
        acc8(a, u0);
    }

    float dsc = rsqrtf((float)(deg + 1));
    float4 b0 = *(const float4*)(bias + lane * 8);
    float4 b1 = *(const float4*)(bias + lane * 8 + 4);
    float o0 = fmaxf(fmaf(dsc, a[0], b0.x), 0.f);
    float o1 = fmaxf(fmaf(dsc, a[1], b0.y), 0.f);
    float o2 = fmaxf(fmaf(dsc, a[2], b0.z), 0.f);
    float o3 = fmaxf(fmaf(dsc, a[3], b0.w), 0.f);
    float o4 = fmaxf(fmaf(dsc, a[4], b1.x), 0.f);
    float o5 = fmaxf(fmaf(dsc, a[5], b1.y), 0.f);
    float o6 = fmaxf(fmaf(dsc, a[6], b1.z), 0.f);
    float o7 = fmaxf(fmaf(dsc, a[7], b1.w), 0.f);

    uint4 w;
    w.x = packbf2(o0, o1); w.y = packbf2(o2, o3);
    w.z = packbf2(o4, o5); w.w = packbf2(o6, o7);
    *(uint4*)(g_Ah + self) = w;
}

// ---------------- launch ----------------
extern "C" void kernel_launch(void* const* d_in, const int* in_sizes, int n_in,
                              void* d_out, int out_size)
{
    const float* x  = (const float*)d_in[0];
    const int*   ei = (const int*)d_in[1];
    const float* W1 = (const float*)d_in[2];
    const float* b1 = (const float*)d_in[3];
    const float* W2 = (const float*)d_in[4];
    const float* b2 = (const float*)d_in[5];
    const float* Wo = (const float*)d_in[6];
    const float* bo = (const float*)d_in[7];
    float* out = (float*)d_out;

    const int* src = ei;
    const int* dst = ei + NE;

    cudaFuncSetAttribute(gemm_mma<0, 128>, cudaFuncAttributeMaxDynamicSharedMemorySize, 81920);
    cudaFuncSetAttribute(gemm_mma<1, 128>, cudaFuncAttributeMaxDynamicSharedMemorySize, 81920);
    cudaFuncSetAttribute(gemm_mma<2, 64>,  cudaFuncAttributeMaxDynamicSharedMemorySize, 61440);

    const int GM = (NN + 127) / 128;   // 782

    k_prep<<<NN * DD / 1024, 256>>>(x, W1, W2, Wo);              // 1: x/W -> bf16, zero deg
    k_deg<<<NE / 256, 256>>>(dst);                               // 2: degrees + edge slots
    k_off<<<(NN + 255) / 256, 256>>>();                          // 3: CSR offsets
    gemm_mma<0, 128><<<dim3(GM, 2), 256, 81920>>>(nullptr, nullptr);  // 4: Hs = dis*(x@W1)
    k_scatter<<<NE / 256, 256>>>(src, dst);                      // 5: CSR fill (no atomics)
    k_agg<<<NN / 8, 256>>>(b1);                                  // 6: Ah = bf16(relu(...))
    gemm_mma<1, 128><<<dim3(GM, 2), 256, 81920>>>(nullptr, nullptr);
    k_agg<<<NN / 8, 256>>>(b2);
    gemm_mma<2, 64><<<dim3(GM, 1), 256, 61440>>>(bo, out);       // out = lsm(h@Wo + bo)
}

// round 16
// speedup vs baseline: 1.3160x; 1.0357x over previous
#include <cuda_runtime.h>
#include <cuda_bf16.h>
#include <cstdint>

#define NN 100000
#define NE 800000
#define DD 256

// ---------------- device scratch (no allocations allowed) ----------------
__device__ __align__(16) __nv_bfloat16 g_Hs[(size_t)NN * DD];   // dis-scaled h (bf16)
__device__ __align__(16) __nv_bfloat16 g_Ah[(size_t)NN * DD];   // A operand bf16 (x / relu out)
__device__ int   g_indeg[NN];
__device__ int   g_off[NN];
__device__ int   g_epos[NE];
__device__ int   g_csrc[NE];
__device__ int   g_total;
// W bf16, pre-transposed to [N][K] (B operand, K-contiguous)
__device__ __align__(16) __nv_bfloat16 g_W1h[256 * 256];
__device__ __align__(16) __nv_bfloat16 g_W2h[256 * 256];
__device__ __align__(16) __nv_bfloat16 g_Woh[64 * 256];

// ---------------- PTX helpers (valid on compute_103) ----------------
__device__ __forceinline__ uint32_t smem_u32(const void* p) {
    uint32_t a;
    asm("{ .reg .u64 t; cvta.to.shared.u64 t, %1; cvt.u32.u64 %0, t; }" : "=r"(a) : "l"(p));
    return a;
}
__device__ __forceinline__ void ldsm4(uint32_t r[4], uint32_t addr) {
    asm volatile("ldmatrix.sync.aligned.m8n8.x4.shared.b16 {%0,%1,%2,%3}, [%4];"
                 : "=r"(r[0]), "=r"(r[1]), "=r"(r[2]), "=r"(r[3]) : "r"(addr));
}
__device__ __forceinline__ void mma16816(float c[4], const uint32_t a[4],
                                         uint32_t b0, uint32_t b1) {
    asm volatile(
        "mma.sync.aligned.m16n8k16.row.col.f32.bf16.bf16.f32 "
        "{%0,%1,%2,%3}, {%4,%5,%6,%7}, {%8,%9}, {%0,%1,%2,%3};"
        : "+f"(c[0]), "+f"(c[1]), "+f"(c[2]), "+f"(c[3])
        : "r"(a[0]), "r"(a[1]), "r"(a[2]), "r"(a[3]), "r"(b0), "r"(b1));
}
__device__ __forceinline__ void cpa16(uint32_t dst, const void* src, int sz) {
    asm volatile("cp.async.cg.shared.global [%0], [%1], 16, %2;"
                 :: "r"(dst), "l"(src), "r"(sz) : "memory");
}
#define CP_COMMIT() asm volatile("cp.async.commit_group;" ::: "memory")
#define CP_WAIT(n)  asm volatile("cp.async.wait_group %0;" :: "n"(n) : "memory")

// pack two fp32 -> one bf16x2 word (round-to-nearest)
__device__ __forceinline__ uint32_t packbf2(float f0, float f1) {
    __nv_bfloat16 h0 = __float2bfloat16(f0), h1 = __float2bfloat16(f1);
    return (uint32_t)*(uint16_t*)&h0 | ((uint32_t)*(uint16_t*)&h1 << 16);
}
__device__ __forceinline__ float2 bf2f(uint32_t w) {
    __nv_bfloat162 b;
    *reinterpret_cast<uint32_t*>(&b) = w;
    return __bfloat1622float2(b);
}
__device__ __forceinline__ void acc8(float* a, uint4 u) {
    float2 f0 = bf2f(u.x), f1 = bf2f(u.y), f2 = bf2f(u.z), f3 = bf2f(u.w);
    a[0] += f0.x; a[1] += f0.y; a[2] += f1.x; a[3] += f1.y;
    a[4] += f2.x; a[5] += f2.y; a[6] += f3.x; a[7] += f3.y;
}

// ---------------- prep: x->bf16, W->bf16 transposed, zero deg ----------------
__global__ void k_prep(const float* __restrict__ x, const float* __restrict__ W1,
                       const float* __restrict__ W2, const float* __restrict__ Wo) {
    int gid = blockIdx.x * 256 + threadIdx.x;
    size_t i = (size_t)gid * 4;
    float4 v = *(const float4*)(x + i);
    *(uint2*)(g_Ah + i) = make_uint2(packbf2(v.x, v.y), packbf2(v.z, v.w));

    if (gid < NN) g_indeg[gid] = 0;
    if (gid == 0) g_total = 0;
    if (gid < 65536) {
        int n = gid >> 8, k = gid & 255;
        g_W1h[gid] = __float2bfloat16(W1[(size_t)k * 256 + n]);
        g_W2h[gid] = __float2bfloat16(W2[(size_t)k * 256 + n]);
        if (gid < 16384) {
            int n2 = gid >> 8, k2 = gid & 255;
            g_Woh[gid] = __float2bfloat16(Wo[(size_t)k2 * 64 + n2]);
        }
    }
}
// degree count + per-edge slot reservation
__global__ void k_deg(const int* __restrict__ dst) {
    int e = blockIdx.x * 256 + threadIdx.x;
    if (e < NE) g_epos[e] = atomicAdd(&g_indeg[dst[e]], 1);
}
// parallel offset assignment: warp scan + one atomic per warp (order-free CSR)
__global__ void k_off() {
    int i = blockIdx.x * 256 + threadIdx.x;
    int lane = threadIdx.x & 31;
    int d = (i < NN) ? g_indeg[i] : 0;
    int v = d;
    #pragma unroll
    for (int s = 1; s < 32; s <<= 1) {
        int t = __shfl_up_sync(0xffffffffu, v, s);
        if (lane >= s) v += t;
    }
    int wtotal = __shfl_sync(0xffffffffu, v, 31);
    int base = 0;
    if (lane == 0) base = atomicAdd(&g_total, wtotal);
    base = __shfl_sync(0xffffffffu, base, 0);
    if (i < NN) g_off[i] = base + v - d;
}
// atomic-free scatter using reserved slots
__global__ void k_scatter(const int* __restrict__ src, const int* __restrict__ dst) {
    int e = blockIdx.x * 256 + threadIdx.x;
    if (e < NE) g_csrc[g_off[dst[e]] + g_epos[e]] = src[e];
}

// ---------------- HMMA GEMM, BK=64, 3-stage cp.async ring, single bf16 pass ---
// BM=128, 256 thr (8 warps 4m x 2n), warp tile 32 x (BN/2). 2 CTAs/SM.
// smem rows: 144B stride (conflict-free ldsm phases).
// MODE 0/1: C=g_Hs (bf16), row-scale by rsqrt(indeg+1)
// MODE 2:   C=Cext (fp32), + bias + fused log_softmax (BN=64)
template <int MODE, int BN>
__global__ __launch_bounds__(256, 2)
void gemm_mma(const float* __restrict__ bias, float* __restrict__ Cext)
{
    const __nv_bfloat16* WH = (MODE == 0) ? g_W1h : (MODE == 1) ? g_W2h : g_Woh;

    constexpr int WN = BN / 2;               // 64 or 32
    constexpr int NT = WN / 8;               // 8 or 4
    constexpr int A_BYTES = 128 * 144;       // 18432 (64 bf16 + pad per row)
    constexpr int B_BYTES = BN * 144;
    constexpr int STAGE = A_BYTES + B_BYTES;
    constexpr int BH = BN / 32;              // B cp.async iters (4 or 2)

    extern __shared__ char smraw[];
    uint32_t sb = smem_u32(smraw);

    int tid = threadIdx.x, lane = tid & 31, wid = tid >> 5;
    int mw = wid & 3, nw = wid >> 2;
    int bm0 = blockIdx.x * 128;
    int bn0 = blockIdx.y * BN;

    auto issue = [&](int kb) {
        uint32_t base = sb + (uint32_t)(kb % 3) * STAGE;
        #pragma unroll
        for (int h = 0; h < 4; h++) {
            int c = tid + h * 256;            // 0..1023
            int row = c >> 3, kq = c & 7;
            int r = bm0 + row;
            uint32_t dst = base + (uint32_t)row * 144u + (uint32_t)kq * 16u;
            size_t gp = (size_t)r * DD + kb * 64 + kq * 8;
            cpa16(dst, g_Ah + gp, (r < NN) ? 16 : 0);
        }
        #pragma unroll
        for (int h = 0; h < BH; h++) {
            int c = tid + h * 256;
            int row = c >> 3, kq = c & 7;
            uint32_t dst = base + A_BYTES + (uint32_t)row * 144u + (uint32_t)kq * 16u;
            size_t gp = (size_t)(bn0 + row) * DD + kb * 64 + kq * 8;
            cpa16(dst, WH + gp, 16);
        }
        CP_COMMIT();
    };

    float acc[2][NT][4];
    #pragma unroll
    for (int mt = 0; mt < 2; mt++)
        #pragma unroll
        for (int nt = 0; nt < NT; nt++)
            #pragma unroll
            for (int q = 0; q < 4; q++) acc[mt][nt][q] = 0.f;

    issue(0); issue(1);

    for (int kb = 0; kb < 4; kb++) {
        CP_WAIT(1);            // chunk kb complete (tail aligned w/ empty groups)
        __syncthreads();       // readers of stage (kb+2)%3 (chunk kb-1) done
        if (kb + 2 < 4) issue(kb + 2); else CP_COMMIT();

        uint32_t base = sb + (uint32_t)(kb % 3) * STAGE;
        #pragma unroll
        for (int ks = 0; ks < 4; ks++) {
            int col = ks * 16 + (lane >> 4) * 8;
            uint32_t ah[2][4];
            uint32_t aoff = base + (uint32_t)((mw * 32 + (lane & 15)) * 144)
                          + (uint32_t)col * 2u;
            ldsm4(ah[0], aoff);
            ldsm4(ah[1], aoff + 16 * 144);

            #pragma unroll
            for (int g = 0; g < NT / 4; g++) {
                uint32_t bh[4][2];
                #pragma unroll
                for (int j2 = 0; j2 < 2; j2++) {
                    int j = g * 2 + j2;
                    uint32_t boff = base + A_BYTES +
                        (uint32_t)((nw * WN + j * 16 + (lane & 15)) * 144) +
                        (uint32_t)col * 2u;
                    uint32_t rh[4];
                    ldsm4(rh, boff);
                    bh[2 * j2][0] = rh[0]; bh[2 * j2][1] = rh[2];
                    bh[2 * j2 + 1][0] = rh[1]; bh[2 * j2 + 1][1] = rh[3];
                }
                #pragma unroll
                for (int mt = 0; mt < 2; mt++)
                    #pragma unroll
                    for (int q = 0; q < 4; q++)
                        mma16816(acc[mt][g * 4 + q], ah[mt], bh[q][0], bh[q][1]);
            }
        }
    }

    if (MODE != 2) {
        // ---- epilogue: dis = rsqrt(indeg+1), scale + bf16 store to g_Hs ----
        int rbase = bm0 + mw * 32 + (lane >> 2);
        int cbase = bn0 + nw * WN + (lane & 3) * 2;
        #pragma unroll
        for (int mt = 0; mt < 2; mt++) {
            int r0 = rbase + mt * 16, r1 = r0 + 8;
            float s0 = (r0 < NN) ? rsqrtf((float)(g_indeg[r0] + 1)) : 0.f;
            float s1 = (r1 < NN) ? rsqrtf((float)(g_indeg[r1] + 1)) : 0.f;
            #pragma unroll
            for (int nt = 0; nt < NT; nt++) {
                int cc = cbase + nt * 8;
                if (r0 < NN) *(uint32_t*)(g_Hs + (size_t)r0 * 256 + cc) =
                    packbf2(acc[mt][nt][0] * s0, acc[mt][nt][1] * s0);
                if (r1 < NN) *(uint32_t*)(g_Hs + (size_t)r1 * 256 + cc) =
                    packbf2(acc[mt][nt][2] * s1, acc[mt][nt][3] * s1);
            }
        }
    } else {
        // ---- epilogue: bias -> smem -> fused log_softmax -> fp32 store ----
        __syncthreads();   // all compute done before smem reuse
        float* ls = (float*)smraw;   // 128 x 64 fp32 = 32KB
        int lr0 = mw * 32 + (lane >> 2);
        int cb = nw * WN + (lane & 3) * 2;
        #pragma unroll
        for (int mt = 0; mt < 2; mt++) {
            int a0 = lr0 + mt * 16, a1 = a0 + 8;
            #pragma unroll
            for (int nt = 0; nt < NT; nt++) {
                int cc = cb + nt * 8;
                float b0 = bias[cc], b1 = bias[cc + 1];
                ls[a0 * 64 + cc] = acc[mt][nt][0] + b0;
                ls[a0 * 64 + cc + 1] = acc[mt][nt][1] + b1;
                ls[a1 * 64 + cc] = acc[mt][nt][2] + b0;
                ls[a1 * 64 + cc + 1] = acc[mt][nt][3] + b1;
            }
        }
        __syncthreads();
        #pragma unroll 1
        for (int i = 0; i < 16; i++) {
            int lr = wid * 16 + i;
            int r = bm0 + lr;
            if (r >= NN) break;
            float2 v = *(const float2*)&ls[lr * 64 + lane * 2];
            float m = fmaxf(v.x, v.y);
            #pragma unroll
            for (int d = 16; d; d >>= 1) m = fmaxf(m, __shfl_xor_sync(0xffffffffu, m, d));
            float sm = expf(v.x - m) + expf(v.y - m);
            #pragma unroll
            for (int d = 16; d; d >>= 1) sm += __shfl_xor_sync(0xffffffffu, sm, d);
            float l = m + logf(sm);
            *(float2*)(Cext + (size_t)r * 64 + lane * 2) = make_float2(v.x - l, v.y - l);
        }
    }
}

// ---------------- aggregation (bf16 gather, MLP=4): relu(dis*(...)+b) -> bf16 ----
__global__ __launch_bounds__(256)
void k_agg(const float* __restrict__ bias)
{
    int node = blockIdx.x * 8 + (threadIdx.x >> 5);
    int lane = threadIdx.x & 31;
    const __nv_bfloat16* __restrict__ Hs = g_Hs;

    size_t self = (size_t)node * 256 + lane * 8;
    float a[8];
    {
        uint4 u = *(const uint4*)(Hs + self);
        float2 f0 = bf2f(u.x), f1 = bf2f(u.y), f2 = bf2f(u.z), f3 = bf2f(u.w);
        a[0] = f0.x; a[1] = f0.y; a[2] = f1.x; a[3] = f1.y;
        a[4] = f2.x; a[5] = f2.y; a[6] = f3.x; a[7] = f3.y;
    }

    int e = g_off[node], deg = g_indeg[node], end = e + deg;
    for (; e + 3 < end; e += 4) {
        int s0 = g_csrc[e], s1 = g_csrc[e + 1], s2 = g_csrc[e + 2], s3 = g_csrc[e + 3];
        uint4 u0 = *(const uint4*)(Hs + (size_t)s0 * 256 + lane * 8);
        uint4 u1 = *(const uint4*)(Hs + (size_t)s1 * 256 + lane * 8);
        uint4 u2 = *(const uint4*)(Hs + (size_t)s2 * 256 + lane * 8);
        uint4 u3 = *(const uint4*)(Hs + (size_t)s3 * 256 + lane * 8);
        acc8(a, u0); acc8(a, u1); acc8(a, u2); acc8(a, u3);
    }
    for (; e < end; e++) {
        uint4 u0 = *(const uint4*)(Hs + (size_t)g_csrc[e] * 256 + lane * 8);
        acc8(a, u0);
    }

    float dsc = rsqrtf((float)(deg + 1));
    float4 b0 = *(const float4*)(bias + lane * 8);
    float4 b1 = *(const float4*)(bias + lane * 8 + 4);
    float o0 = fmaxf(fmaf(dsc, a[0], b0.x), 0.f);
    float o1 = fmaxf(fmaf(dsc, a[1], b0.y), 0.f);
    float o2 = fmaxf(fmaf(dsc, a[2], b0.z), 0.f);
    float o3 = fmaxf(fmaf(dsc, a[3], b0.w), 0.f);
    float o4 = fmaxf(fmaf(dsc, a[4], b1.x), 0.f);
    float o5 = fmaxf(fmaf(dsc, a[5], b1.y), 0.f);
    float o6 = fmaxf(fmaf(dsc, a[6], b1.z), 0.f);
    float o7 = fmaxf(fmaf(dsc, a[7], b1.w), 0.f);

    uint4 w;
    w.x = packbf2(o0, o1); w.y = packbf2(o2, o3);
    w.z = packbf2(o4, o5); w.w = packbf2(o6, o7);
    *(uint4*)(g_Ah + self) = w;
}

// ---------------- launch ----------------
extern "C" void kernel_launch(void* const* d_in, const int* in_sizes, int n_in,
                              void* d_out, int out_size)
{
    const float* x  = (const float*)d_in[0];
    const int*   ei = (const int*)d_in[1];
    const float* W1 = (const float*)d_in[2];
    const float* b1 = (const float*)d_in[3];
    const float* W2 = (const float*)d_in[4];
    const float* b2 = (const float*)d_in[5];
    const float* Wo = (const float*)d_in[6];
    const float* bo = (const float*)d_in[7];
    float* out = (float*)d_out;

    const int* src = ei;
    const int* dst = ei + NE;

    constexpr int SM01 = 3 * (128 * 144 + 128 * 144);   // 110592
    constexpr int SM2  = 3 * (128 * 144 + 64 * 144);    // 82944
    cudaFuncSetAttribute(gemm_mma<0, 128>, cudaFuncAttributeMaxDynamicSharedMemorySize, SM01);
    cudaFuncSetAttribute(gemm_mma<1, 128>, cudaFuncAttributeMaxDynamicSharedMemorySize, SM01);
    cudaFuncSetAttribute(gemm_mma<2, 64>,  cudaFuncAttributeMaxDynamicSharedMemorySize, SM2);

    const int GM = (NN + 127) / 128;   // 782

    k_prep<<<NN * DD / 1024, 256>>>(x, W1, W2, Wo);              // 1: x/W -> bf16, zero deg
    k_deg<<<NE / 256, 256>>>(dst);                               // 2: degrees + edge slots
    k_off<<<(NN + 255) / 256, 256>>>();                          // 3: CSR offsets
    gemm_mma<0, 128><<<dim3(GM, 2), 256, SM01>>>(nullptr, nullptr);  // 4: Hs = dis*(x@W1)
    k_scatter<<<NE / 256, 256>>>(src, dst);                      // 5: CSR fill (no atomics)
    k_agg<<<NN / 8, 256>>>(b1);                                  // 6: Ah = bf16(relu(...))
    gemm_mma<1, 128><<<dim3(GM, 2), 256, SM01>>>(nullptr, nullptr);
    k_agg<<<NN / 8, 256>>>(b2);
    gemm_mma<2, 64><<<dim3(GM, 1), 256, SM2>>>(bo, out);         // out = lsm(h@Wo + bo)
}